// round 6
// baseline (speedup 1.0000x reference)
#include <cuda_runtime.h>
#include <cstdint>

#define NVIEW 8
#define HH 480
#define WW 640
#define HW (HH*WW)            // 307200
#define CIN 14
#define PPT 2                 // pixels per thread
#define NGROUP (NVIEW*HW/PPT) // 1228800
#define BLK 128
#define SLOT 34               // 30 floats used + 4 pad (float2-aligned, 2-way STS conflicts)
#define CHUNK (BLK*PPT*15)    // floats of output per block = 3840

// per-view constants: invK[9], R[9], t[3], mult  (padded to 24)
__device__ float g_vc[NVIEW * 24];

__global__ void precompute_kernel(const float* __restrict__ ext,
                                  const float* __restrict__ intr) {
    int v = threadIdx.x;
    if (v >= NVIEW) return;
    const float* K = intr + v * 9;
    float K0=K[0],K1=K[1],K2=K[2],K3=K[3],K4=K[4],K5=K[5],K6=K[6],K7=K[7],K8=K[8];
    float det = K0*(K4*K8-K5*K7) - K1*(K3*K8-K5*K6) + K2*(K3*K7-K4*K6);
    float id = 1.0f / det;
    float* o = g_vc + v * 24;
    o[0]=(K4*K8-K5*K7)*id;
    o[1]=(K2*K7-K1*K8)*id;
    o[2]=(K1*K5-K2*K4)*id;
    o[3]=(K5*K6-K3*K8)*id;
    o[4]=(K0*K8-K2*K6)*id;
    o[5]=(K2*K3-K0*K5)*id;
    o[6]=(K3*K7-K4*K6)*id;
    o[7]=(K1*K6-K0*K7)*id;
    o[8]=(K0*K4-K1*K3)*id;
    const float* E = ext + v * 16;
    o[9]=E[0];  o[10]=E[1]; o[11]=E[2];
    o[12]=E[4]; o[13]=E[5]; o[14]=E[6];
    o[15]=E[8]; o[16]=E[9]; o[17]=E[10];
    o[18]=E[3]; o[19]=E[7]; o[20]=E[11];
    // mult = sum(inv(K[:2,:2])) = (a+d-b-c)/det2
    o[21] = (K0 + K4 - K1 - K3) / (K0*K4 - K1*K3);
    o[22] = 0.f; o[23] = 0.f;
}

__device__ __forceinline__ float sigmoidf(float x) {
    return __fdividef(1.f, 1.f + __expf(-x));
}
__device__ __forceinline__ float softplusf(float x) {
    return fmaxf(x, 0.f) + __logf(1.f + __expf(-fabsf(x)));
}
__device__ __forceinline__ float getc(float2 a, int j) {
    return (j == 0) ? a.x : a.y;
}

__global__ __launch_bounds__(BLK, 8)
void decoder_kernel(const float* __restrict__ raw, float* __restrict__ out) {
    __shared__ float sbuf[BLK * SLOT];   // 17408 B

    int tid = threadIdx.x;
    int g = blockIdx.x * BLK + tid;
    int pix0  = g * PPT;
    int v     = pix0 / HW;
    int local = pix0 - v * HW;
    int h     = local / WW;
    int w0    = local - h * WW;

    const float* vc = g_vc + v * 24;
    float iK0=vc[0], iK1=vc[1], iK2=vc[2], iK3=vc[3], iK4=vc[4],
          iK5=vc[5], iK6=vc[6], iK7=vc[7], iK8=vc[8];
    float R00=vc[9],  R01=vc[10], R02=vc[11],
          R10=vc[12], R11=vc[13], R12=vc[14],
          R20=vc[15], R21=vc[16], R22=vc[17];
    float t0=vc[18], t1=vc[19], t2=vc[20], mult=vc[21];

    // load 14 channel float2s (2 adjacent w pixels); 256B/warp dense per LDG
    const float2* base2 = reinterpret_cast<const float2*>(
        raw + (size_t)v * CIN * HW + local);
    float2 in[CIN];
#pragma unroll
    for (int c = 0; c < CIN; c++) in[c] = base2[c * (HW / 2)];

    float* slot = sbuf + tid * SLOT;
#pragma unroll
    for (int j = 0; j < PPT; j++) {
        float* o = slot + 15 * j;

        // ray through (pixel + sigmoid(offset) - 0.5)
        float px = (float)(w0 + j) + sigmoidf(getc(in[12], j)) - 0.5f;
        float py = (float)h        + sigmoidf(getc(in[13], j)) - 0.5f;
        float dx = iK0 * px + iK1 * py + iK2;
        float dy = iK3 * px + iK4 * py + iK5;
        float dz = iK6 * px + iK7 * py + iK8;
        float rn = rsqrtf(dx*dx + dy*dy + dz*dz);
        dx *= rn; dy *= rn; dz *= rn;
        float wxd = R00*dx + R01*dy + R02*dz;
        float wyd = R10*dx + R11*dy + R12*dz;
        float wzd = R20*dx + R21*dy + R22*dz;

        // depth from disparity
        float sd = sigmoidf(getc(in[3], j));
        float depth = __fdividef(1.0f, sd * 19.95f + 0.05f); // 1/NEAR-1/FAR, 1/FAR

        o[0] = t0 + wxd * depth;
        o[1] = t1 + wyd * depth;
        o[2] = t2 + wzd * depth;
        o[3] = 1.0f;                     // homogeneous component of means

        o[4] = softplusf(getc(in[0], j));
        o[5] = softplusf(getc(in[1], j));
        o[6] = softplusf(getc(in[2], j));
        o[7] = sigmoidf(getc(in[4], j));
        o[8]  = softplusf(getc(in[5], j)) * mult;
        o[9]  = softplusf(getc(in[6], j)) * mult;
        o[10] = softplusf(getc(in[7], j)) * mult;

        // quaternion (x,y,z,w) -> rotation, compose with extrinsic R, back to quat (wxyz)
        float qx = getc(in[8], j), qy = getc(in[9], j),
              qz = getc(in[10], j), qw = getc(in[11], j);
        float qn = rsqrtf(qx*qx + qy*qy + qz*qz + qw*qw);
        qx *= qn; qy *= qn; qz *= qn; qw *= qn;
        float xx = qx*qx, yy = qy*qy, zz = qz*qz;
        float xy = qx*qy, xz = qx*qz, yz = qy*qz;
        float xw = qx*qw, yw = qy*qw, zw = qz*qw;
        float M00 = 1.f - 2.f*(yy + zz), M01 = 2.f*(xy - zw), M02 = 2.f*(xz + yw);
        float M10 = 2.f*(xy + zw), M11 = 1.f - 2.f*(xx + zz), M12 = 2.f*(yz - xw);
        float M20 = 2.f*(xz - yw), M21 = 2.f*(yz + xw), M22 = 1.f - 2.f*(xx + yy);

        float W00 = R00*M00 + R01*M10 + R02*M20;
        float W01 = R00*M01 + R01*M11 + R02*M21;
        float W02 = R00*M02 + R01*M12 + R02*M22;
        float W10 = R10*M00 + R11*M10 + R12*M20;
        float W11 = R10*M01 + R11*M11 + R12*M21;
        float W12 = R10*M02 + R11*M12 + R12*M22;
        float W20 = R20*M00 + R21*M10 + R22*M20;
        float W21 = R20*M01 + R21*M11 + R22*M21;
        float W22 = R20*M02 + R21*M12 + R22*M22;

        float tr = W00 + W11 + W22;
        // first-max argmax over [W00, W11, W22, tr]
        int   ch = 0;  float best = W00;
        if (W11 > best) { best = W11; ch = 1; }
        if (W22 > best) { best = W22; ch = 2; }
        if (tr  > best) { ch = 3; }

        float qa, qb, qc, qd;
        if (ch == 0) {
            qa = W21 - W12; qb = 1.f + W00 - W11 - W22;
            qc = W01 + W10; qd = W02 + W20;
        } else if (ch == 1) {
            qa = W02 - W20; qb = W01 + W10;
            qc = 1.f + W11 - W00 - W22; qd = W12 + W21;
        } else if (ch == 2) {
            qa = W10 - W01; qb = W02 + W20;
            qc = W12 + W21; qd = 1.f + W22 - W00 - W11;
        } else {
            qa = 1.f + tr;  qb = W21 - W12;
            qc = W02 - W20; qd = W10 - W01;
        }
        float qrn = rsqrtf(qa*qa + qb*qb + qc*qc + qd*qd);
        o[11] = qa * qrn; o[12] = qb * qrn; o[13] = qc * qrn; o[14] = qd * qrn;
    }

    __syncthreads();

    // Dense store phase: block chunk = 3840 contiguous floats = 1920 float2.
    // Each iteration: 128 threads x float2 = 1024B fully contiguous in gmem
    // -> every STG.64 is 256B/warp dense (minimum wavefronts).
    float2* out2 = reinterpret_cast<float2*>(out + (size_t)blockIdx.x * CHUNK);
#pragma unroll
    for (int it = 0; it < 15; it++) {
        int u   = it * BLK + tid;   // float2 index within chunk
        int src = u / 15;           // source thread slot (30 floats = 15 float2 each)
        int r   = u - src * 15;     // float2 within slot
        float2 val = *reinterpret_cast<const float2*>(sbuf + src * SLOT + 2 * r);
        out2[u] = val;
    }
}

extern "C" void kernel_launch(void* const* d_in, const int* in_sizes, int n_in,
                              void* d_out, int out_size) {
    const float* raw  = (const float*)d_in[0];  // (1,8,14,480,640)
    const float* ext  = (const float*)d_in[1];  // (1,8,4,4)
    const float* intr = (const float*)d_in[2];  // (1,8,3,3)
    float* out = (float*)d_out;                 // (8,480,640,15)

    precompute_kernel<<<1, NVIEW>>>(ext, intr);
    decoder_kernel<<<NGROUP / BLK, BLK>>>(raw, out);
}

// round 10
// speedup vs baseline: 1.0689x; 1.0689x over previous
#include <cuda_runtime.h>
#include <cstdint>

#define NVIEW 8
#define HH 480
#define WW 640
#define HW (HH*WW)            // 307200
#define CIN 14
#define PPT 4                 // pixels per thread
#define NGROUP (NVIEW*HW/PPT) // 614400
#define BLK 128
#define SLOT 60               // compact: no padding -> linear conflict-free LDS.128 reads
#define CHUNK (BLK*PPT*15)    // floats of output per block = 7680

__device__ __forceinline__ float tanh_approx(float x) {
    float y;
    asm("tanh.approx.f32 %0, %1;" : "=f"(y) : "f"(x));
    return y;
}
__device__ __forceinline__ float sigmoidf(float x) {
    return fmaf(0.5f, tanh_approx(0.5f * x), 0.5f);
}
__device__ __forceinline__ float softplusf(float x) {
    return fmaxf(x, 0.f) + __logf(1.f + __expf(-fabsf(x)));
}
__device__ __forceinline__ float getc(float4 a, int j) {
    return (j == 0) ? a.x : (j == 1) ? a.y : (j == 2) ? a.z : a.w;
}

__global__ __launch_bounds__(BLK, 7)
void decoder_kernel(const float* __restrict__ raw,
                    const float* __restrict__ ext,
                    const float* __restrict__ intr,
                    float* __restrict__ out) {
    __shared__ float sbuf[BLK * SLOT];   // 30720 B -> 7 blocks/SM = 215KB

    int tid = threadIdx.x;
    int g = blockIdx.x * BLK + tid;
    int pix0  = g * PPT;
    int v     = pix0 / HW;               // uniform within block (512 px never crosses views)
    int local = pix0 - v * HW;
    int h     = local / WW;
    int w0    = local - h * WW;

    // ---- per-view constants, computed in-thread (uniform broadcast loads) ----
    const float* K = intr + v * 9;
    float K0=K[0],K1=K[1],K2=K[2],K3=K[3],K4=K[4],K5=K[5],K6=K[6],K7=K[7],K8=K[8];
    float det = K0*(K4*K8-K5*K7) - K1*(K3*K8-K5*K6) + K2*(K3*K7-K4*K6);
    float id  = __fdividef(1.0f, det);
    float iK0=(K4*K8-K5*K7)*id, iK1=(K2*K7-K1*K8)*id, iK2=(K1*K5-K2*K4)*id;
    float iK3=(K5*K6-K3*K8)*id, iK4=(K0*K8-K2*K6)*id, iK5=(K2*K3-K0*K5)*id;
    float iK6=(K3*K7-K4*K6)*id, iK7=(K1*K6-K0*K7)*id, iK8=(K0*K4-K1*K3)*id;
    float mult = __fdividef(K0 + K4 - K1 - K3, K0*K4 - K1*K3);

    const float* E = ext + v * 16;
    float R00=E[0], R01=E[1],  R02=E[2],  t0=E[3],
          R10=E[4], R11=E[5],  R12=E[6],  t1=E[7],
          R20=E[8], R21=E[9],  R22=E[10], t2=E[11];

    // ---- load 14 channel float4s (4 adjacent w pixels), perfectly coalesced ----
    const float4* base4 = reinterpret_cast<const float4*>(
        raw + (size_t)v * CIN * HW + local);
    float4 in[CIN];
#pragma unroll
    for (int c = 0; c < CIN; c++) in[c] = base4[c * (HW / 4)];

    float* slot = sbuf + tid * SLOT;
#pragma unroll
    for (int j = 0; j < PPT; j++) {
        float* o = slot + 15 * j;

        // ray through (pixel + sigmoid(offset) - 0.5)
        float px = (float)(w0 + j) + sigmoidf(getc(in[12], j)) - 0.5f;
        float py = (float)h        + sigmoidf(getc(in[13], j)) - 0.5f;
        float dx = iK0 * px + iK1 * py + iK2;
        float dy = iK3 * px + iK4 * py + iK5;
        float dz = iK6 * px + iK7 * py + iK8;
        float rn = rsqrtf(dx*dx + dy*dy + dz*dz);
        dx *= rn; dy *= rn; dz *= rn;
        float wxd = R00*dx + R01*dy + R02*dz;
        float wyd = R10*dx + R11*dy + R12*dz;
        float wzd = R20*dx + R21*dy + R22*dz;

        // depth from disparity
        float sd = sigmoidf(getc(in[3], j));
        float depth = __fdividef(1.0f, sd * 19.95f + 0.05f); // 1/NEAR-1/FAR, 1/FAR

        o[0] = t0 + wxd * depth;
        o[1] = t1 + wyd * depth;
        o[2] = t2 + wzd * depth;
        o[3] = 1.0f;                     // homogeneous component of means

        o[4] = softplusf(getc(in[0], j));
        o[5] = softplusf(getc(in[1], j));
        o[6] = softplusf(getc(in[2], j));
        o[7] = sigmoidf(getc(in[4], j));
        o[8]  = softplusf(getc(in[5], j)) * mult;
        o[9]  = softplusf(getc(in[6], j)) * mult;
        o[10] = softplusf(getc(in[7], j)) * mult;

        // quaternion (x,y,z,w) -> rotation, compose with extrinsic R, back to quat (wxyz)
        float qx = getc(in[8], j), qy = getc(in[9], j),
              qz = getc(in[10], j), qw = getc(in[11], j);
        float qn = rsqrtf(qx*qx + qy*qy + qz*qz + qw*qw);
        qx *= qn; qy *= qn; qz *= qn; qw *= qn;
        float xx = qx*qx, yy = qy*qy, zz = qz*qz;
        float xy = qx*qy, xz = qx*qz, yz = qy*qz;
        float xw = qx*qw, yw = qy*qw, zw = qz*qw;
        float M00 = 1.f - 2.f*(yy + zz), M01 = 2.f*(xy - zw), M02 = 2.f*(xz + yw);
        float M10 = 2.f*(xy + zw), M11 = 1.f - 2.f*(xx + zz), M12 = 2.f*(yz - xw);
        float M20 = 2.f*(xz - yw), M21 = 2.f*(yz + xw), M22 = 1.f - 2.f*(xx + yy);

        float W00 = R00*M00 + R01*M10 + R02*M20;
        float W01 = R00*M01 + R01*M11 + R02*M21;
        float W02 = R00*M02 + R01*M12 + R02*M22;
        float W10 = R10*M00 + R11*M10 + R12*M20;
        float W11 = R10*M01 + R11*M11 + R12*M21;
        float W12 = R10*M02 + R11*M12 + R12*M22;
        float W20 = R20*M00 + R21*M10 + R22*M20;
        float W21 = R20*M01 + R21*M11 + R22*M21;
        float W22 = R20*M02 + R21*M12 + R22*M22;

        float tr = W00 + W11 + W22;
        // first-max argmax over [W00, W11, W22, tr]
        int   ch = 0;  float best = W00;
        if (W11 > best) { best = W11; ch = 1; }
        if (W22 > best) { best = W22; ch = 2; }
        if (tr  > best) { ch = 3; }

        float qa, qb, qc, qd;
        if (ch == 0) {
            qa = W21 - W12; qb = 1.f + W00 - W11 - W22;
            qc = W01 + W10; qd = W02 + W20;
        } else if (ch == 1) {
            qa = W02 - W20; qb = W01 + W10;
            qc = 1.f + W11 - W00 - W22; qd = W12 + W21;
        } else if (ch == 2) {
            qa = W10 - W01; qb = W02 + W20;
            qc = W12 + W21; qd = 1.f + W22 - W00 - W11;
        } else {
            qa = 1.f + tr;  qb = W21 - W12;
            qc = W02 - W20; qd = W10 - W01;
        }
        float qrn = rsqrtf(qa*qa + qb*qb + qc*qc + qd*qd);
        o[11] = qa * qrn; o[12] = qb * qrn; o[13] = qc * qrn; o[14] = qd * qrn;
    }

    __syncthreads();

    // Dense store phase: compact staging (SLOT==60) means shared reads are
    // purely linear: lane reads float4 at sbuf[f], f = it*512 + tid*4 ->
    // conflict-free LDS.128, and every STG.128 is 512B/warp dense.
    float4* out4 = reinterpret_cast<float4*>(out + (size_t)blockIdx.x * CHUNK);
    const float4* s4 = reinterpret_cast<const float4*>(sbuf);
#pragma unroll
    for (int it = 0; it < 15; it++) {
        out4[it * BLK + tid] = s4[it * BLK + tid];
    }
}

extern "C" void kernel_launch(void* const* d_in, const int* in_sizes, int n_in,
                              void* d_out, int out_size) {
    const float* raw  = (const float*)d_in[0];  // (1,8,14,480,640)
    const float* ext  = (const float*)d_in[1];  // (1,8,4,4)
    const float* intr = (const float*)d_in[2];  // (1,8,3,3)
    float* out = (float*)d_out;                 // (8,480,640,15)

    decoder_kernel<<<NGROUP / BLK, BLK>>>(raw, ext, intr, out);
}

// round 11
// speedup vs baseline: 1.1351x; 1.0619x over previous
#include <cuda_runtime.h>
#include <cstdint>

#define NVIEW 8
#define HH 480
#define WW 640
#define HW (HH*WW)            // 307200
#define CIN 14
#define PPT 4                 // pixels per thread
#define NGROUP (NVIEW*HW/PPT) // 614400
#define BLK 128
#define SLOT 60               // compact, no padding
#define WSLICE (32*SLOT)      // 1920 floats per warp slice
#define CHUNK (BLK*PPT*15)    // floats of output per block = 7680

__device__ __forceinline__ float tanh_approx(float x) {
    float y;
    asm("tanh.approx.f32 %0, %1;" : "=f"(y) : "f"(x));
    return y;
}
__device__ __forceinline__ float sigmoidf(float x) {
    return fmaf(0.5f, tanh_approx(0.5f * x), 0.5f);
}
__device__ __forceinline__ float softplusf(float x) {
    return fmaxf(x, 0.f) + __logf(1.f + __expf(-fabsf(x)));
}
__device__ __forceinline__ float getc(float4 a, int j) {
    return (j == 0) ? a.x : (j == 1) ? a.y : (j == 2) ? a.z : a.w;
}

__global__ __launch_bounds__(BLK, 7)
void decoder_kernel(const float* __restrict__ raw,
                    const float* __restrict__ ext,
                    const float* __restrict__ intr,
                    float* __restrict__ out) {
    __shared__ float sbuf[BLK * SLOT];   // 30720 B -> 7 blocks/SM = 215KB

    int tid  = threadIdx.x;
    int wid  = tid >> 5;                 // warp in block (0..3)
    int lane = tid & 31;
    int g = blockIdx.x * BLK + tid;
    int pix0  = g * PPT;
    int v     = pix0 / HW;               // uniform within block (512 px never crosses views)
    int local = pix0 - v * HW;
    int h     = local / WW;
    int w0    = local - h * WW;

    // ---- per-view constants, computed in-thread (uniform broadcast loads) ----
    const float* K = intr + v * 9;
    float K0=K[0],K1=K[1],K2=K[2],K3=K[3],K4=K[4],K5=K[5],K6=K[6],K7=K[7],K8=K[8];
    float det = K0*(K4*K8-K5*K7) - K1*(K3*K8-K5*K6) + K2*(K3*K7-K4*K6);
    float id  = __fdividef(1.0f, det);
    float iK0=(K4*K8-K5*K7)*id, iK1=(K2*K7-K1*K8)*id, iK2=(K1*K5-K2*K4)*id;
    float iK3=(K5*K6-K3*K8)*id, iK4=(K0*K8-K2*K6)*id, iK5=(K2*K3-K0*K5)*id;
    float iK6=(K3*K7-K4*K6)*id, iK7=(K1*K6-K0*K7)*id, iK8=(K0*K4-K1*K3)*id;
    float mult = __fdividef(K0 + K4 - K1 - K3, K0*K4 - K1*K3);

    const float* E = ext + v * 16;
    float R00=E[0], R01=E[1],  R02=E[2],  t0=E[3],
          R10=E[4], R11=E[5],  R12=E[6],  t1=E[7],
          R20=E[8], R21=E[9],  R22=E[10], t2=E[11];

    // ---- load 14 channel float4s (4 adjacent w pixels), perfectly coalesced ----
    const float4* base4 = reinterpret_cast<const float4*>(
        raw + (size_t)v * CIN * HW + local);
    float4 in[CIN];
#pragma unroll
    for (int c = 0; c < CIN; c++) in[c] = base4[c * (HW / 4)];

    // warp-local staging slice: this warp's output region is self-contained
    float* slot = sbuf + wid * WSLICE + lane * SLOT;
#pragma unroll
    for (int j = 0; j < PPT; j++) {
        float* o = slot + 15 * j;

        // ray through (pixel + sigmoid(offset) - 0.5)
        float px = (float)(w0 + j) + sigmoidf(getc(in[12], j)) - 0.5f;
        float py = (float)h        + sigmoidf(getc(in[13], j)) - 0.5f;
        float dx = iK0 * px + iK1 * py + iK2;
        float dy = iK3 * px + iK4 * py + iK5;
        float dz = iK6 * px + iK7 * py + iK8;
        float rn = rsqrtf(dx*dx + dy*dy + dz*dz);
        dx *= rn; dy *= rn; dz *= rn;
        float wxd = R00*dx + R01*dy + R02*dz;
        float wyd = R10*dx + R11*dy + R12*dz;
        float wzd = R20*dx + R21*dy + R22*dz;

        // depth from disparity
        float sd = sigmoidf(getc(in[3], j));
        float depth = __fdividef(1.0f, sd * 19.95f + 0.05f); // 1/NEAR-1/FAR, 1/FAR

        o[0] = t0 + wxd * depth;
        o[1] = t1 + wyd * depth;
        o[2] = t2 + wzd * depth;
        o[3] = 1.0f;                     // homogeneous component of means

        o[4] = softplusf(getc(in[0], j));
        o[5] = softplusf(getc(in[1], j));
        o[6] = softplusf(getc(in[2], j));
        o[7] = sigmoidf(getc(in[4], j));
        o[8]  = softplusf(getc(in[5], j)) * mult;
        o[9]  = softplusf(getc(in[6], j)) * mult;
        o[10] = softplusf(getc(in[7], j)) * mult;

        // quaternion (x,y,z,w) -> rotation, compose with extrinsic R, back to quat (wxyz)
        float qx = getc(in[8], j), qy = getc(in[9], j),
              qz = getc(in[10], j), qw = getc(in[11], j);
        float qn = rsqrtf(qx*qx + qy*qy + qz*qz + qw*qw);
        qx *= qn; qy *= qn; qz *= qn; qw *= qn;
        float xx = qx*qx, yy = qy*qy, zz = qz*qz;
        float xy = qx*qy, xz = qx*qz, yz = qy*qz;
        float xw = qx*qw, yw = qy*qw, zw = qz*qw;
        float M00 = 1.f - 2.f*(yy + zz), M01 = 2.f*(xy - zw), M02 = 2.f*(xz + yw);
        float M10 = 2.f*(xy + zw), M11 = 1.f - 2.f*(xx + zz), M12 = 2.f*(yz - xw);
        float M20 = 2.f*(xz - yw), M21 = 2.f*(yz + xw), M22 = 1.f - 2.f*(xx + yy);

        float W00 = R00*M00 + R01*M10 + R02*M20;
        float W01 = R00*M01 + R01*M11 + R02*M21;
        float W02 = R00*M02 + R01*M12 + R02*M22;
        float W10 = R10*M00 + R11*M10 + R12*M20;
        float W11 = R10*M01 + R11*M11 + R12*M21;
        float W12 = R10*M02 + R11*M12 + R12*M22;
        float W20 = R20*M00 + R21*M10 + R22*M20;
        float W21 = R20*M01 + R21*M11 + R22*M21;
        float W22 = R20*M02 + R21*M12 + R22*M22;

        float tr = W00 + W11 + W22;
        // first-max argmax over [W00, W11, W22, tr]
        int   ch = 0;  float best = W00;
        if (W11 > best) { best = W11; ch = 1; }
        if (W22 > best) { best = W22; ch = 2; }
        if (tr  > best) { ch = 3; }

        float qa, qb, qc, qd;
        if (ch == 0) {
            qa = W21 - W12; qb = 1.f + W00 - W11 - W22;
            qc = W01 + W10; qd = W02 + W20;
        } else if (ch == 1) {
            qa = W02 - W20; qb = W01 + W10;
            qc = 1.f + W11 - W00 - W22; qd = W12 + W21;
        } else if (ch == 2) {
            qa = W10 - W01; qb = W02 + W20;
            qc = W12 + W21; qd = 1.f + W22 - W00 - W11;
        } else {
            qa = 1.f + tr;  qb = W21 - W12;
            qc = W02 - W20; qd = W10 - W01;
        }
        float qrn = rsqrtf(qa*qa + qb*qb + qc*qc + qd*qd);
        o[11] = qa * qrn; o[12] = qb * qrn; o[13] = qc * qrn; o[14] = qd * qrn;
    }

    // Warp-local handoff: this warp's 1920-float slice covers exactly its own
    // contiguous 7680B gmem region -> no block barrier needed.
    __syncwarp();

    // Dense store phase: per warp, 480 float4 linear in smem and gmem.
    // Each STG.128 is 512B/warp dense; __stcs = evict-first (write-once stream).
    float4* out4 = reinterpret_cast<float4*>(
        out + (size_t)blockIdx.x * CHUNK + wid * WSLICE);
    const float4* s4 = reinterpret_cast<const float4*>(sbuf + wid * WSLICE);
#pragma unroll
    for (int it = 0; it < 15; it++) {
        __stcs(out4 + it * 32 + lane, s4[it * 32 + lane]);
    }
}

extern "C" void kernel_launch(void* const* d_in, const int* in_sizes, int n_in,
                              void* d_out, int out_size) {
    const float* raw  = (const float*)d_in[0];  // (1,8,14,480,640)
    const float* ext  = (const float*)d_in[1];  // (1,8,4,4)
    const float* intr = (const float*)d_in[2];  // (1,8,3,3)
    float* out = (float*)d_out;                 // (8,480,640,15)

    decoder_kernel<<<NGROUP / BLK, BLK>>>(raw, ext, intr, out);
}